// round 5
// baseline (speedup 1.0000x reference)
#include <cuda_runtime.h>
#include <cstdint>

typedef unsigned long long ull;

#define DIN   4096
#define NM    8
#define NH    512
#define NOUT  10

// bf16 hi/lo pre-converted W1 diagonal blocks: [m][512 rows][512 k]
__device__ unsigned short g_w1hi[8u * 512u * 512u];
__device__ unsigned short g_w1lo[8u * 512u * 512u];

// ---- dynamic smem layout (bytes) ----
#define STAGE_STRIDE 40960u
#define T_AHI        0u
#define T_ALO        10240u
#define T_BHI        20480u
#define T_BLO        30720u
#define OFF_HBUF     81920u      // 128 * 132 * 4 = 67584
#define HPITCH       132
#define OFF_W2       149504u     // 512 * 12 * 4 = 24576
#define OFF_B1       174080u     // 512 * 4
#define SMEM_TOTAL   176128u

// named barriers (counts are all 256)
#define BFULL0  1
#define BFULL1  2
#define BEMPTY0 3
#define BEMPTY1 4
#define BHFULL  5
#define BHEMPTY 6
#define BAR_SYNC(id)   asm volatile("bar.sync %0, 256;"   :: "r"(id) : "memory")
#define BAR_ARRIVE(id) asm volatile("bar.arrive %0, 256;" :: "r"(id) : "memory")
#define MEMBAR_CTA()   asm volatile("membar.cta;" ::: "memory")

static __device__ __forceinline__ uint32_t smem_u32(const void* p) {
    uint32_t a;
    asm("{ .reg .u64 t; cvta.to.shared.u64 t, %1; cvt.u32.u64 %0, t; }"
        : "=r"(a) : "l"(p));
    return a;
}
static __device__ __forceinline__ void ldsm4(uint32_t* r, uint32_t addr) {
    asm volatile("ldmatrix.sync.aligned.m8n8.x4.shared.b16 {%0,%1,%2,%3}, [%4];"
                 : "=r"(r[0]), "=r"(r[1]), "=r"(r[2]), "=r"(r[3]) : "r"(addr));
}
static __device__ __forceinline__ void mma16816(float* d, const uint32_t* a,
                                                uint32_t b0, uint32_t b1) {
    asm volatile("mma.sync.aligned.m16n8k16.row.col.f32.bf16.bf16.f32 "
                 "{%0,%1,%2,%3}, {%4,%5,%6,%7}, {%8,%9}, {%0,%1,%2,%3};"
                 : "+f"(d[0]), "+f"(d[1]), "+f"(d[2]), "+f"(d[3])
                 : "r"(a[0]), "r"(a[1]), "r"(a[2]), "r"(a[3]), "r"(b0), "r"(b1));
}
static __device__ __forceinline__ void cp16(uint32_t dst, const void* src) {
    asm volatile("cp.async.cg.shared.global [%0], [%1], 16;"
                 :: "r"(dst), "l"(src) : "memory");
}
static __device__ __forceinline__ void cp_commit() {
    asm volatile("cp.async.commit_group;" ::: "memory");
}
static __device__ __forceinline__ void cp_wait0() {
    asm volatile("cp.async.wait_group 0;" ::: "memory");
}
static __device__ __forceinline__ ull packdup(float v) {
    ull r;
    asm("mov.b64 %0, {%1, %1};" : "=l"(r) : "r"(__float_as_uint(v)));
    return r;
}
static __device__ __forceinline__ void fma2(ull& d, ull a, ull b) {
    asm("fma.rn.f32x2 %0, %1, %2, %0;" : "+l"(d) : "l"(a), "l"(b));
}
static __device__ __forceinline__ void split4(float4 v, uint32_t& h01, uint32_t& h23,
                                              uint32_t& l01, uint32_t& l23) {
    asm("cvt.rn.bf16x2.f32 %0, %1, %2;" : "=r"(h01) : "f"(v.y), "f"(v.x));
    asm("cvt.rn.bf16x2.f32 %0, %1, %2;" : "=r"(h23) : "f"(v.w), "f"(v.z));
    float f0 = __uint_as_float(h01 << 16);
    float f1 = __uint_as_float(h01 & 0xffff0000u);
    float f2 = __uint_as_float(h23 << 16);
    float f3 = __uint_as_float(h23 & 0xffff0000u);
    asm("cvt.rn.bf16x2.f32 %0, %1, %2;" : "=r"(l01) : "f"(v.y - f1), "f"(v.x - f0));
    asm("cvt.rn.bf16x2.f32 %0, %1, %2;" : "=r"(l23) : "f"(v.w - f3), "f"(v.z - f2));
}
static __device__ __forceinline__ void sts8(uint32_t addr, uint32_t a, uint32_t b) {
    asm volatile("st.shared.v2.b32 [%0], {%1,%2};" :: "r"(addr), "r"(a), "r"(b) : "memory");
}

// ---------------- pre-pass: W1 diag blocks -> bf16 hi/lo ----------------
__global__ __launch_bounds__(256)
void cvt_w1(const float* __restrict__ W1) {
    int g = blockIdx.x * 256 + threadIdx.x;
    int m = g >> 16;
    int rem = g & 65535;
    int r = rem >> 7;
    int c4 = rem & 127;
    float4 v = *(const float4*)(W1 + (size_t)(m * 512 + r) * DIN + m * 512 + c4 * 4);
    uint32_t h01, h23, l01, l23;
    split4(v, h01, h23, l01, l23);
    size_t off = ((size_t)(m * 512 + r) * 512 + c4 * 4);
    *(uint2*)(g_w1hi + off) = make_uint2(h01, h23);
    *(uint2*)(g_w1lo + off) = make_uint2(l01, l23);
}

// ---------------- fused, warp-specialized main kernel ----------------
__global__ __launch_bounds__(256, 1)
void fused_ws(const float* __restrict__ x,  const float* __restrict__ b1,
              const float* __restrict__ W2, const float* __restrict__ b2,
              float* __restrict__ y) {
    extern __shared__ char smem[];
    const uint32_t sb = smem_u32(smem);
    const int tid  = threadIdx.x;
    const int lane = tid & 31;
    const int m       = blockIdx.y;
    const int rowBase = blockIdx.x * 128;

    float* w2s  = (float*)(smem + OFF_W2);
    float* b1s  = (float*)(smem + OFF_B1);
    float* hbuf = (float*)(smem + OFF_HBUF);

    for (int i = tid; i < NH; i += 256) b1s[i] = b1[m * NH + i];
    for (int idx = tid; idx < NH * 12; idx += 256) {
        int c = idx / 12, o = idx - c * 12;
        w2s[idx] = (o < NOUT) ? W2[(size_t)(m * NOUT + o) * DIN + m * NH + c] : 0.f;
    }
    __syncthreads();

    if (tid < 128) {
        // ================= CONSUMERS: 4 warps, 64x64 tiles =================
        const int wid = tid >> 5;
        const int wm = wid & 1;
        const int wn = wid >> 1;
        const uint32_t lmoff = (uint32_t)(lane & 15) * 80u + (uint32_t)(lane >> 4) * 16u;

        for (int p = 0; p < 4; p++) {
            float acc[4][8][4];
            #pragma unroll
            for (int i = 0; i < 4; i++)
                #pragma unroll
                for (int j = 0; j < 8; j++)
                    #pragma unroll
                    for (int q = 0; q < 4; q++) acc[i][j][q] = 0.f;

            for (int c = 0; c < 16; c++) {
                const int g = p * 16 + c;
                const int b = g & 1;
                BAR_SYNC(BFULL0 + b);
                const uint32_t base = sb + (uint32_t)b * STAGE_STRIDE;
                #pragma unroll
                for (int ks = 0; ks < 2; ks++) {
                    uint32_t ah[4][4], al[4][4];
                    #pragma unroll
                    for (int i = 0; i < 4; i++) {
                        uint32_t off = (uint32_t)(wm * 64 + i * 16) * 80u + ks * 32u + lmoff;
                        ldsm4(ah[i], base + T_AHI + off);
                        ldsm4(al[i], base + T_ALO + off);
                    }
                    #pragma unroll
                    for (int jh = 0; jh < 2; jh++) {
                        uint32_t bhf[4][2], blf[4][2];
                        #pragma unroll
                        for (int jj = 0; jj < 2; jj++) {
                            uint32_t off = (uint32_t)(wn * 64 + jh * 32 + jj * 16) * 80u
                                         + ks * 32u + lmoff;
                            uint32_t rh[4], rl[4];
                            ldsm4(rh, base + T_BHI + off);
                            ldsm4(rl, base + T_BLO + off);
                            bhf[2 * jj][0] = rh[0];     bhf[2 * jj][1] = rh[2];
                            bhf[2 * jj + 1][0] = rh[1]; bhf[2 * jj + 1][1] = rh[3];
                            blf[2 * jj][0] = rl[0];     blf[2 * jj][1] = rl[2];
                            blf[2 * jj + 1][0] = rl[1]; blf[2 * jj + 1][1] = rl[3];
                        }
                        #pragma unroll
                        for (int i = 0; i < 4; i++)
                            #pragma unroll
                            for (int j = 0; j < 4; j++) {
                                float* A_ = acc[i][jh * 4 + j];
                                mma16816(A_, ah[i], bhf[j][0], bhf[j][1]);
                                mma16816(A_, ah[i], blf[j][0], blf[j][1]);
                                mma16816(A_, al[i], bhf[j][0], bhf[j][1]);
                            }
                    }
                }
                BAR_ARRIVE(BEMPTY0 + b);
            }

            // epilogue: bias + relu -> hbuf
            BAR_SYNC(BHEMPTY);
            #pragma unroll
            for (int i = 0; i < 4; i++) {
                int r0 = wm * 64 + i * 16 + (lane >> 2);
                #pragma unroll
                for (int jc = 0; jc < 8; jc++) {
                    int c0 = wn * 64 + jc * 8 + 2 * (lane & 3);
                    float bb0 = b1s[p * 128 + c0], bb1 = b1s[p * 128 + c0 + 1];
                    float2 v0, v1;
                    v0.x = fmaxf(acc[i][jc][0] + bb0, 0.f);
                    v0.y = fmaxf(acc[i][jc][1] + bb1, 0.f);
                    v1.x = fmaxf(acc[i][jc][2] + bb0, 0.f);
                    v1.y = fmaxf(acc[i][jc][3] + bb1, 0.f);
                    *(float2*)(hbuf + (size_t)r0 * HPITCH + c0) = v0;
                    *(float2*)(hbuf + (size_t)(r0 + 8) * HPITCH + c0) = v1;
                }
            }
            MEMBAR_CTA();
            BAR_ARRIVE(BHFULL);
        }
    } else {
        // ================= PRODUCERS: 4 warps =================
        const int ptid = tid - 128;
        const float* xb = x + (size_t)rowBase * DIN + m * NH;

        auto stage = [&](int p2, int k0, uint32_t buf) {
            // B hi/lo via cp.async (issue first — async)
            #pragma unroll
            for (int s = 0; s < 8; s++) {
                int hl = s >> 2;
                int fr = ptid + (s & 3) * 128;
                int br = fr >> 2, c4 = fr & 3;
                const unsigned short* src = (hl ? g_w1lo : g_w1hi)
                    + ((size_t)(m * 512 + p2 * 128 + br) * 512 + k0 + c4 * 8);
                cp16(buf + (hl ? T_BLO : T_BHI)
                     + (uint32_t)br * 80u + (uint32_t)c4 * 16u, src);
            }
            cp_commit();
            // A: LDG fp32 + split + STS
            #pragma unroll
            for (int s = 0; s < 8; s++) {
                int f = ptid + s * 128;
                int row = f >> 3, kq = f & 7;
                float4 v = *(const float4*)(xb + (size_t)row * DIN + k0 + kq * 4);
                uint32_t h01, h23, l01, l23;
                split4(v, h01, h23, l01, l23);
                uint32_t off = (uint32_t)row * 80u + (uint32_t)kq * 8u;
                sts8(buf + T_AHI + off, h01, h23);
                sts8(buf + T_ALO + off, l01, l23);
            }
        };

        ull acc2[5] = {0, 0, 0, 0, 0};
        auto layer2 = [&](int pp) {
            BAR_SYNC(BHFULL);
            const float* hrow = hbuf + (size_t)ptid * HPITCH;
            #pragma unroll 4
            for (int cc = 0; cc < 128; cc += 4) {
                float4 h4 = *(const float4*)(hrow + cc);
                float hv[4] = {h4.x, h4.y, h4.z, h4.w};
                #pragma unroll
                for (int u = 0; u < 4; u++) {
                    ull hp = packdup(hv[u]);
                    const ull* wp = (const ull*)(w2s + (size_t)(pp * 128 + cc + u) * 12);
                    fma2(acc2[0], hp, wp[0]);
                    fma2(acc2[1], hp, wp[1]);
                    fma2(acc2[2], hp, wp[2]);
                    fma2(acc2[3], hp, wp[3]);
                    fma2(acc2[4], hp, wp[4]);
                }
            }
            BAR_ARRIVE(BHEMPTY);
        };

        BAR_ARRIVE(BHEMPTY);   // hbuf starts empty

        int g = 0;
        for (int p = 0; p < 4; p++) {
            for (int c = 0; c < 16; c++, g++) {
                const int b = g & 1;
                if (g >= 2) BAR_SYNC(BEMPTY0 + b);
                stage(p, c * 32, sb + (uint32_t)b * STAGE_STRIDE);
                cp_wait0();
                MEMBAR_CTA();
                BAR_ARRIVE(BFULL0 + b);
                if (c == 1 && p >= 1) layer2(p - 1);
            }
        }
        layer2(3);

        // each producer thread owns one output row
        float* yp = y + (size_t)(rowBase + ptid) * (NM * NOUT) + m * NOUT;
        #pragma unroll
        for (int q5 = 0; q5 < 5; q5++) {
            float2 v;
            v.x = __uint_as_float((uint32_t)(acc2[q5] & 0xffffffffu)) + b2[m * NOUT + 2 * q5];
            v.y = __uint_as_float((uint32_t)(acc2[q5] >> 32)) + b2[m * NOUT + 2 * q5 + 1];
            ((float2*)yp)[q5] = v;
        }
    }
}

extern "C" void kernel_launch(void* const* d_in, const int* in_sizes, int n_in,
                              void* d_out, int out_size) {
    const float* x  = (const float*)d_in[0];
    const float* W1 = (const float*)d_in[1];
    const float* b1 = (const float*)d_in[2];
    const float* W2 = (const float*)d_in[3];
    const float* b2 = (const float*)d_in[4];
    float* y = (float*)d_out;

    cvt_w1<<<2048, 256>>>(W1);

    cudaFuncSetAttribute(fused_ws,
                         cudaFuncAttributeMaxDynamicSharedMemorySize, SMEM_TOTAL);
    dim3 grid(8192 / 128, NM);   // 512 CTAs
    fused_ws<<<grid, 256, SMEM_TOTAL>>>(x, b1, W2, b2, y);
}

// round 6
// speedup vs baseline: 1.7528x; 1.7528x over previous
#include <cuda_runtime.h>
#include <cuda_fp16.h>
#include <cstdint>

typedef unsigned long long ull;

#define DIN   4096
#define NM    8
#define NH    512
#define NOUT  10

// fp16 pre-converted W1 diagonal blocks: [m][512 rows][512 k]
__device__ __half g_w1h[8u * 512u * 512u];

// ---- dynamic smem layout (bytes): 4-deep stage ring ----
#define STAGE_STRIDE 20480u      // per buffer: A 128*80, B 128*80
#define T_A          0u
#define T_B          10240u
#define OFF_HBUF     81920u      // 128 * 132 * 4 = 67584
#define HPITCH       132
#define OFF_W2       149504u     // 512 * 12 * 4 = 24576
#define OFF_B1       174080u
#define SMEM_TOTAL   176128u

// named barriers
#define BFULL(s)   (1 + (s))
#define BEMPTY(s)  (5 + (s))
#define BHFULL     9
#define BHEMPTY    10
#define BAR_SYNC(id)   asm volatile("bar.sync %0, 256;"   :: "r"(id) : "memory")
#define BAR_ARRIVE(id) asm volatile("bar.arrive %0, 256;" :: "r"(id) : "memory")
#define MEMBAR_CTA()   asm volatile("membar.cta;" ::: "memory")

static __device__ __forceinline__ uint32_t smem_u32(const void* p) {
    uint32_t a;
    asm("{ .reg .u64 t; cvta.to.shared.u64 t, %1; cvt.u32.u64 %0, t; }"
        : "=r"(a) : "l"(p));
    return a;
}
static __device__ __forceinline__ void ldsm4(uint32_t* r, uint32_t addr) {
    asm volatile("ldmatrix.sync.aligned.m8n8.x4.shared.b16 {%0,%1,%2,%3}, [%4];"
                 : "=r"(r[0]), "=r"(r[1]), "=r"(r[2]), "=r"(r[3]) : "r"(addr));
}
static __device__ __forceinline__ void mma16816f(float* d, const uint32_t* a,
                                                 uint32_t b0, uint32_t b1) {
    asm volatile("mma.sync.aligned.m16n8k16.row.col.f32.f16.f16.f32 "
                 "{%0,%1,%2,%3}, {%4,%5,%6,%7}, {%8,%9}, {%0,%1,%2,%3};"
                 : "+f"(d[0]), "+f"(d[1]), "+f"(d[2]), "+f"(d[3])
                 : "r"(a[0]), "r"(a[1]), "r"(a[2]), "r"(a[3]), "r"(b0), "r"(b1));
}
static __device__ __forceinline__ void cp16(uint32_t dst, const void* src) {
    asm volatile("cp.async.cg.shared.global [%0], [%1], 16;"
                 :: "r"(dst), "l"(src) : "memory");
}
static __device__ __forceinline__ void cp_commit() {
    asm volatile("cp.async.commit_group;" ::: "memory");
}
static __device__ __forceinline__ void cp_wait1() {
    asm volatile("cp.async.wait_group 1;" ::: "memory");
}
static __device__ __forceinline__ void cp_wait0() {
    asm volatile("cp.async.wait_group 0;" ::: "memory");
}
static __device__ __forceinline__ ull packdup(float v) {
    ull r;
    asm("mov.b64 %0, {%1, %1};" : "=l"(r) : "r"(__float_as_uint(v)));
    return r;
}
static __device__ __forceinline__ void fma2(ull& d, ull a, ull b) {
    asm("fma.rn.f32x2 %0, %1, %2, %0;" : "+l"(d) : "l"(a), "l"(b));
}
static __device__ __forceinline__ void sts8(uint32_t addr, uint32_t a, uint32_t b) {
    asm volatile("st.shared.v2.b32 [%0], {%1,%2};" :: "r"(addr), "r"(a), "r"(b) : "memory");
}
static __device__ __forceinline__ void cvt4(float4 v, uint32_t& p01, uint32_t& p23) {
    __half2 a = __floats2half2_rn(v.x, v.y);
    __half2 b = __floats2half2_rn(v.z, v.w);
    p01 = *(uint32_t*)&a;
    p23 = *(uint32_t*)&b;
}

// ---------------- pre-pass: W1 diag blocks -> fp16 ----------------
__global__ __launch_bounds__(256)
void cvt_w1(const float* __restrict__ W1) {
    int g = blockIdx.x * 256 + threadIdx.x;    // 524288 float4s
    int m = g >> 16;
    int rem = g & 65535;
    int r = rem >> 7;
    int c4 = rem & 127;
    float4 v = *(const float4*)(W1 + (size_t)(m * 512 + r) * DIN + m * 512 + c4 * 4);
    uint32_t p01, p23;
    cvt4(v, p01, p23);
    *(uint2*)(g_w1h + ((size_t)(m * 512 + r) * 512 + c4 * 4)) = make_uint2(p01, p23);
}

// ---------------- fused, warp-specialized fp16 kernel ----------------
__global__ __launch_bounds__(256, 1)
void fused_f16(const float* __restrict__ x,  const float* __restrict__ b1,
               const float* __restrict__ W2, const float* __restrict__ b2,
               float* __restrict__ y) {
    extern __shared__ char smem[];
    const uint32_t sb = smem_u32(smem);
    const int tid  = threadIdx.x;
    const int lane = tid & 31;
    const int m       = blockIdx.y;
    const int rowBase = blockIdx.x * 128;

    float* w2s  = (float*)(smem + OFF_W2);
    float* b1s  = (float*)(smem + OFF_B1);
    float* hbuf = (float*)(smem + OFF_HBUF);

    for (int i = tid; i < NH; i += 256) b1s[i] = b1[m * NH + i];
    for (int idx = tid; idx < NH * 12; idx += 256) {
        int c = idx / 12, o = idx - c * 12;
        w2s[idx] = (o < NOUT) ? W2[(size_t)(m * NOUT + o) * DIN + m * NH + c] : 0.f;
    }
    __syncthreads();

    if (tid < 128) {
        // ============ CONSUMERS: 4 warps, 64x64 tiles, single fp16 term ============
        const int wid = tid >> 5;
        const int wm = wid & 1;
        const int wn = wid >> 1;
        const uint32_t lmoff = (uint32_t)(lane & 15) * 80u + (uint32_t)(lane >> 4) * 16u;

        for (int p = 0; p < 4; p++) {
            float acc[4][8][4];
            #pragma unroll
            for (int i = 0; i < 4; i++)
                #pragma unroll
                for (int j = 0; j < 8; j++)
                    #pragma unroll
                    for (int q = 0; q < 4; q++) acc[i][j][q] = 0.f;

            for (int c = 0; c < 16; c++) {
                const int g = p * 16 + c;
                const int s = g & 3;
                BAR_SYNC(BFULL(s));
                const uint32_t base = sb + (uint32_t)s * STAGE_STRIDE;
                #pragma unroll
                for (int ks = 0; ks < 2; ks++) {
                    uint32_t af[4][4];
                    #pragma unroll
                    for (int i = 0; i < 4; i++) {
                        uint32_t off = (uint32_t)(wm * 64 + i * 16) * 80u + ks * 32u + lmoff;
                        ldsm4(af[i], base + T_A + off);
                    }
                    #pragma unroll
                    for (int jh = 0; jh < 2; jh++) {
                        uint32_t bf[4][2];
                        #pragma unroll
                        for (int jj = 0; jj < 2; jj++) {
                            uint32_t off = (uint32_t)(wn * 64 + jh * 32 + jj * 16) * 80u
                                         + ks * 32u + lmoff;
                            uint32_t rh[4];
                            ldsm4(rh, base + T_B + off);
                            bf[2 * jj][0] = rh[0];     bf[2 * jj][1] = rh[2];
                            bf[2 * jj + 1][0] = rh[1]; bf[2 * jj + 1][1] = rh[3];
                        }
                        #pragma unroll
                        for (int i = 0; i < 4; i++)
                            #pragma unroll
                            for (int j = 0; j < 4; j++)
                                mma16816f(acc[i][jh * 4 + j], af[i], bf[j][0], bf[j][1]);
                    }
                }
                BAR_ARRIVE(BEMPTY(s));
            }

            // epilogue: bias + relu -> hbuf
            BAR_SYNC(BHEMPTY);
            #pragma unroll
            for (int i = 0; i < 4; i++) {
                int r0 = wm * 64 + i * 16 + (lane >> 2);
                #pragma unroll
                for (int jc = 0; jc < 8; jc++) {
                    int c0 = wn * 64 + jc * 8 + 2 * (lane & 3);
                    float bb0 = b1s[p * 128 + c0], bb1 = b1s[p * 128 + c0 + 1];
                    float2 v0, v1;
                    v0.x = fmaxf(acc[i][jc][0] + bb0, 0.f);
                    v0.y = fmaxf(acc[i][jc][1] + bb1, 0.f);
                    v1.x = fmaxf(acc[i][jc][2] + bb0, 0.f);
                    v1.y = fmaxf(acc[i][jc][3] + bb1, 0.f);
                    *(float2*)(hbuf + (size_t)r0 * HPITCH + c0) = v0;
                    *(float2*)(hbuf + (size_t)(r0 + 8) * HPITCH + c0) = v1;
                }
            }
            MEMBAR_CTA();
            BAR_ARRIVE(BHFULL);
        }
    } else {
        // ============ PRODUCERS: 4 warps — staging + fused layer 2 ============
        const int ptid = tid - 128;
        const float* xb = x + (size_t)rowBase * DIN + m * NH;

        // B stage: 4 cp16 per thread
        auto stageB = [&](int g, uint32_t buf) {
            const int p2 = g >> 4, k0 = (g & 15) * 32;
            #pragma unroll
            for (int j = 0; j < 4; j++) {
                int f = ptid + j * 128;
                int br = f >> 2, c4 = f & 3;
                const __half* src = g_w1h
                    + ((size_t)(m * 512 + p2 * 128 + br) * 512 + k0 + c4 * 8);
                cp16(buf + T_B + (uint32_t)br * 80u + (uint32_t)c4 * 16u, src);
            }
            cp_commit();
        };
        // A load: 8 float4 per thread -> regs
        auto loadA = [&](int g, float4* av) {
            const int k0 = (g & 15) * 32;
            #pragma unroll
            for (int s2 = 0; s2 < 8; s2++) {
                int f = ptid + s2 * 128;
                int row = f >> 3, kq = f & 7;
                av[s2] = *(const float4*)(xb + (size_t)row * DIN + k0 + kq * 4);
            }
        };
        auto stsA = [&](uint32_t buf, const float4* av) {
            #pragma unroll
            for (int s2 = 0; s2 < 8; s2++) {
                int f = ptid + s2 * 128;
                int row = f >> 3, kq = f & 7;
                uint32_t p01, p23;
                cvt4(av[s2], p01, p23);
                sts8(buf + T_A + (uint32_t)row * 80u + (uint32_t)kq * 8u, p01, p23);
            }
        };

        ull acc2[5] = {0, 0, 0, 0, 0};
        auto layer2 = [&](int pp) {
            BAR_SYNC(BHFULL);
            const float* hrow = hbuf + (size_t)ptid * HPITCH;
            #pragma unroll 4
            for (int cc = 0; cc < 128; cc += 4) {
                float4 h4 = *(const float4*)(hrow + cc);
                float hv[4] = {h4.x, h4.y, h4.z, h4.w};
                #pragma unroll
                for (int u = 0; u < 4; u++) {
                    ull hp = packdup(hv[u]);
                    const ull* wp = (const ull*)(w2s + (size_t)(pp * 128 + cc + u) * 12);
                    fma2(acc2[0], hp, wp[0]);
                    fma2(acc2[1], hp, wp[1]);
                    fma2(acc2[2], hp, wp[2]);
                    fma2(acc2[3], hp, wp[3]);
                    fma2(acc2[4], hp, wp[4]);
                }
            }
            BAR_ARRIVE(BHEMPTY);
        };

        BAR_ARRIVE(BHEMPTY);   // hbuf starts empty

        float4 av[8];
        // prologue: fully stage chunk 0
        stageB(0, sb);
        loadA(0, av);
        stsA(sb, av);

        for (int g = 0; g < 64; g++) {
            if (g < 63) {
                const int s2 = (g + 1) & 3;
                if (g + 1 >= 4) BAR_SYNC(BEMPTY(s2));
                stageB(g + 1, sb + (uint32_t)s2 * STAGE_STRIDE);
                loadA(g + 1, av);
                cp_wait1();            // chunk g's B group done; g+1 pending
            } else {
                cp_wait0();
            }
            MEMBAR_CTA();
            BAR_ARRIVE(BFULL(g & 3));
            if (g < 63) stsA(sb + (uint32_t)((g + 1) & 3) * STAGE_STRIDE, av);
            if ((g & 15) == 1 && g >= 17) layer2((g >> 4) - 1);
        }
        layer2(3);

        float* yp = y + (size_t)(rowBase + ptid) * (NM * NOUT) + m * NOUT;
        #pragma unroll
        for (int q5 = 0; q5 < 5; q5++) {
            float2 v;
            v.x = __uint_as_float((uint32_t)(acc2[q5] & 0xffffffffu)) + b2[m * NOUT + 2 * q5];
            v.y = __uint_as_float((uint32_t)(acc2[q5] >> 32)) + b2[m * NOUT + 2 * q5 + 1];
            ((float2*)yp)[q5] = v;
        }
    }
}

extern "C" void kernel_launch(void* const* d_in, const int* in_sizes, int n_in,
                              void* d_out, int out_size) {
    const float* x  = (const float*)d_in[0];
    const float* W1 = (const float*)d_in[1];
    const float* b1 = (const float*)d_in[2];
    const float* W2 = (const float*)d_in[3];
    const float* b2 = (const float*)d_in[4];
    float* y = (float*)d_out;

    cvt_w1<<<2048, 256>>>(W1);

    cudaFuncSetAttribute(fused_f16,
                         cudaFuncAttributeMaxDynamicSharedMemorySize, SMEM_TOTAL);
    dim3 grid(8192 / 128, NM);   // 512 CTAs
    fused_f16<<<grid, 256, SMEM_TOTAL>>>(x, b1, W2, b2, y);
}